// round 14
// baseline (speedup 1.0000x reference)
#include <cuda_runtime.h>
#include <cuda_fp16.h>
#include <math.h>
#include <cstdint>

#define NB 4
#define NT 2048
#define NC 1024
#define NH 128
#define NE 16
#define NN (NB*NT)   // 8192 tokens

// ---------------- scratch (static device allocations; no runtime alloc) ----
static __device__ float g_sn[NC*NE];
static __device__ float g_sig[NE];
static __device__ int   g_nact[NN];
static __device__ unsigned char g_tok_e[NN*NE];
static __device__ float g_tok_w[NN*NE];
static __device__ int   g_cnt[NE];
static __device__ int   g_off[NE];
static __device__ int   g_cur[NE];
static __device__ int   g_pair_tok[NN*NE];
static __device__ float g_pair_w[NN*NE];
static __device__ float g_q[NN*NH];
static __device__ float g_k[NN*NH];
static __device__ float g_v[NN*NH];
static __device__ float g_pdot[4*NN*NE];   // split-K gating partials
static __device__ float g_pssq[4*NN];

// packed fp16x2 operand arrays (A-side split hi/lo; B-side rounded single)
static __device__ uint32_t g_xh[NN*NC/2],  g_xl[NN*NC/2];        // X (A, split)
static __device__ uint32_t g_wh[3*NE*NC*NH/2];                   // qkv proj (B)
static __device__ uint32_t g_oph[NE*NH*NC/2];                    // o proj (B)
static __device__ uint32_t g_qh[NN*NH/2], g_ql[NN*NH/2];         // Q (A, split)
static __device__ uint32_t g_kh[NN*NH/2];                        // K (B)
static __device__ uint32_t g_vh[NN*NH/2];                        // V (B)
static __device__ uint32_t g_oh[NN*NH/2], g_ol[NN*NH/2];         // attn out (A, split)

// ================= helpers ==================================================
__device__ __forceinline__ uint32_t smem_u32(const void* p){
    uint32_t a;
    asm("{ .reg .u64 t; cvta.to.shared.u64 t, %1; cvt.u32.u64 %0, t; }" : "=r"(a) : "l"(p));
    return a;
}
__device__ __forceinline__ void split_pairh(float x, float y, uint32_t& hi, uint32_t& lo){
    __half2 h = __floats2half2_rn(x, y);
    float rx = x - __low2float(h);
    float ry = y - __high2float(h);
    __half2 l = __floats2half2_rn(rx, ry);
    hi = *(uint32_t*)&h;
    lo = *(uint32_t*)&l;
}
__device__ __forceinline__ uint32_t round_pairh(float x, float y){
    __half2 h = __floats2half2_rn(x, y);
    return *(uint32_t*)&h;
}
#define CP16(dst,src) asm volatile("cp.async.ca.shared.global [%0], [%1], 16;" :: "r"(dst), "l"(src))
#define CP_COMMIT()   asm volatile("cp.async.commit_group;" ::: "memory")
#define CP_WAIT(n)    asm volatile("cp.async.wait_group %0;" :: "n"(n) : "memory")
#define LDM4(r0,r1,r2,r3,addr) \
    asm volatile("ldmatrix.sync.aligned.m8n8.x4.shared.b16 {%0,%1,%2,%3}, [%4];" \
        : "=r"(r0),"=r"(r1),"=r"(r2),"=r"(r3) : "r"(addr))
#define LDM4T(r0,r1,r2,r3,addr) \
    asm volatile("ldmatrix.sync.aligned.m8n8.x4.trans.shared.b16 {%0,%1,%2,%3}, [%4];" \
        : "=r"(r0),"=r"(r1),"=r"(r2),"=r"(r3) : "r"(addr))
__device__ __forceinline__ void mma16(float c[4],
        uint32_t a0,uint32_t a1,uint32_t a2,uint32_t a3,
        uint32_t b0,uint32_t b1){
    asm volatile("mma.sync.aligned.m16n8k16.row.col.f32.f16.f16.f32 "
        "{%0,%1,%2,%3}, {%4,%5,%6,%7}, {%8,%9}, {%0,%1,%2,%3};"
        : "+f"(c[0]),"+f"(c[1]),"+f"(c[2]),"+f"(c[3])
        : "r"(a0),"r"(a1),"r"(a2),"r"(a3),"r"(b0),"r"(b1));
}

// ---------------- zero / init ----------------
__global__ void zero_kernel(float* __restrict__ out){
    long i = (long)blockIdx.x*blockDim.x + threadIdx.x;
    long stride = (long)gridDim.x*blockDim.x;
    for(long j=i;j<(long)NN*NH;j+=stride){ g_q[j]=0.f; g_k[j]=0.f; g_v[j]=0.f; }
    for(long j=i;j<(long)NN*NC;j+=stride) out[j]=0.f;
    if(i<NE) g_cnt[(int)i]=0;
}

// ---------------- sim-matrix column normalization + sigmoid(gates) ---------
__global__ void prep_kernel(const float* __restrict__ sim, const float* __restrict__ gates){
    int e = blockIdx.x;
    __shared__ float red[256];
    float ss=0.f;
    for(int c=threadIdx.x;c<NC;c+=256){ float v=sim[c*NE+e]; ss+=v*v; }
    red[threadIdx.x]=ss; __syncthreads();
    for(int s=128;s>0;s>>=1){ if(threadIdx.x<s) red[threadIdx.x]+=red[threadIdx.x+s]; __syncthreads(); }
    float inv = 1.f/fmaxf(sqrtf(red[0]),1e-12f);
    for(int c=threadIdx.x;c<NC;c+=256) g_sn[c*NE+e]=sim[c*NE+e]*inv;
    if(threadIdx.x==0) g_sig[e]=1.f/(1.f+expf(-gates[e]));
}

// ---------------- weight pre-pack (fp16 rounded, B-side only) --------------
__global__ void conv_w_kernel(const float* __restrict__ qp, const float* __restrict__ kp,
                              const float* __restrict__ vp, const float* __restrict__ op){
    const long NW_QKV = (long)3*NE*NC*NH/2;
    const long NW_OP  = (long)NE*NH*NC/2;
    const long PERP   = (long)NE*NC*NH/2;
    long stride = (long)gridDim.x*blockDim.x;
    for(long idx = (long)blockIdx.x*blockDim.x + threadIdx.x; idx < NW_QKV+NW_OP; idx += stride){
        if(idx < NW_QKV){
            long p = idx / PERP;
            long r = idx - p*PERP;
            const float* src = (p==0? qp : (p==1? kp : vp)) + r*2;
            float2 v = *(const float2*)src;
            g_wh[idx] = round_pairh(v.x,v.y);
        } else {
            long r = idx - NW_QKV;
            float2 v = *(const float2*)(op + r*2);
            g_oph[r] = round_pairh(v.x,v.y);
        }
    }
}

// ---------------- X pack: fp32 -> fp16 hi/lo (pure streaming) --------------
__global__ void __launch_bounds__(256) pack_x_kernel(const float* __restrict__ X){
    const long NW = (long)NN*NC/4;
    long stride = (long)gridDim.x*blockDim.x;
    for(long idx = (long)blockIdx.x*blockDim.x + threadIdx.x; idx < NW; idx += stride){
        float4 v = *(const float4*)(X + idx*4);
        uint32_t h0,l0,h1,l1;
        split_pairh(v.x,v.y,h0,l0);
        split_pairh(v.z,v.w,h1,l1);
        *(uint2*)(g_xh + idx*2) = make_uint2(h0,h1);
        *(uint2*)(g_xl + idx*2) = make_uint2(l0,l1);
    }
}

// ---------------- gating v4: split-K, loads batched, no stores in loop -----
#define GT3_ESTR 68
#define GT3_SECT 1096

__global__ void __launch_bounds__(256) gate4_kernel(const float* __restrict__ X){
    __shared__ float sns[4*GT3_SECT];
    int tid = threadIdx.x;
    int kz = blockIdx.y;
    for(int i=tid; i<16*256; i+=256){
        int e = i>>8, c = i&255;
        sns[(c>>6)*GT3_SECT + e*GT3_ESTR + (c&63)] = g_sn[(kz*256 + c)*NE + e];
    }
    __syncthreads();

    int part = tid&3, tl = tid>>2;
    int token = blockIdx.x*64 + tl;
    const float4* x4 = (const float4*)(X + (long)token*NC + kz*256 + part*64);
    const float* snp = sns + part*GT3_SECT;

    float ssq = 0.f, dot[NE];
    #pragma unroll
    for(int e=0;e<NE;e++) dot[e]=0.f;

    #pragma unroll
    for(int h=0; h<2; h++){
        float4 xv[8];
        #pragma unroll
        for(int i=0;i<8;i++) xv[i] = x4[h*8 + i];
        #pragma unroll
        for(int i=0;i<8;i++){
            float4 v = xv[i];
            ssq += v.x*v.x + v.y*v.y + v.z*v.z + v.w*v.w;
            const float* sp = snp + (h*8+i)*4;
            #pragma unroll
            for(int e=0;e<NE;e++){
                float4 s = *(const float4*)(sp + e*GT3_ESTR);
                dot[e] += v.x*s.x + v.y*s.y + v.z*s.z + v.w*s.w;
            }
        }
    }
    #pragma unroll
    for(int off=1; off<4; off<<=1){
        ssq += __shfl_xor_sync(0xffffffffu, ssq, off);
        #pragma unroll
        for(int e=0;e<NE;e++) dot[e] += __shfl_xor_sync(0xffffffffu, dot[e], off);
    }
    if(part==0){
        g_pssq[kz*NN + token] = ssq;
        float* pd = g_pdot + ((long)kz*NN + token)*NE;
        #pragma unroll
        for(int e4=0;e4<4;e4++)
            *(float4*)(pd + e4*4) = make_float4(dot[e4*4],dot[e4*4+1],dot[e4*4+2],dot[e4*4+3]);
    }
}

// ---------------- gating finalize ------------------------------------------
__global__ void __launch_bounds__(256) gatefin_kernel(){
    int token = blockIdx.x*256 + threadIdx.x;
    if(token >= NN) return;
    float ssq = 0.f, dot[NE];
    #pragma unroll
    for(int e=0;e<NE;e++) dot[e]=0.f;
    #pragma unroll
    for(int kz=0;kz<4;kz++){
        ssq += g_pssq[kz*NN + token];
        const float* pd = g_pdot + ((long)kz*NN + token)*NE;
        #pragma unroll
        for(int e4=0;e4<4;e4++){
            float4 d = *(const float4*)(pd + e4*4);
            dot[e4*4+0]+=d.x; dot[e4*4+1]+=d.y; dot[e4*4+2]+=d.z; dot[e4*4+3]+=d.w;
        }
    }
    float inv = 1.f/fmaxf(sqrtf(ssq),1e-12f);
    float logit[NE];
    #pragma unroll
    for(int e=0;e<NE;e++) logit[e] = dot[e]*inv - g_sig[e];
    int act[NE]; int na=0;
    for(int e=0;e<NE;e++) if(logit[e]>0.f) act[na++]=e;
    if(na==0){
        int i1=0;
        for(int e=1;e<NE;e++) if(logit[e]>logit[i1]) i1=e;
        int i2=-1;
        for(int e=0;e<NE;e++) if(e!=i1 && (i2<0 || logit[e]>logit[i2])) i2=e;
        int a = i1<i2? i1:i2; int b2 = i1<i2? i2:i1;
        act[0]=a; act[1]=b2; na=2;
    }
    float vals[NE]; float mx=-1e30f;
    for(int k=0;k<na;k++){ vals[k]=fmaxf(logit[act[k]],0.f); mx=fmaxf(mx,vals[k]); }
    float sum=0.f;
    for(int k=0;k<na;k++){ vals[k]=expf(vals[k]-mx); sum+=vals[k]; }
    float isum = 1.f/sum;
    g_nact[token]=na;
    for(int k=0;k<na;k++){
        g_tok_e[token*NE+k]=(unsigned char)act[k];
        g_tok_w[token*NE+k]=vals[k]*isum;
        atomicAdd(&g_cnt[act[k]],1);
    }
}

__global__ void scan_kernel(){
    if(threadIdx.x==0){
        int o=0;
        for(int e=0;e<NE;e++){ g_off[e]=o; o+=g_cnt[e]; }
    }
    if(threadIdx.x<NE) g_cur[threadIdx.x]=0;
}

__global__ void pairfill_kernel(){
    int n = blockIdx.x*blockDim.x + threadIdx.x;
    if(n>=NN) return;
    int na=g_nact[n];
    for(int k=0;k<na;k++){
        int e=g_tok_e[n*NE+k];
        int s=atomicAdd(&g_cur[e],1);
        int p=g_off[e]+s;
        g_pair_tok[p]=n;
        g_pair_w[p]=g_tok_w[n*NE+k];
    }
}

// ---------------- q/k/v fp32 -> fp16 (Q split+scaled; K,V rounded) ---------
__global__ void conv_qkv_kernel(){
    const float scale = 0.0883883476483184f;  // 1/sqrt(128)
    long idx = (long)blockIdx.x*blockDim.x + threadIdx.x;
    if(idx >= (long)NN*NH/2) return;
    uint32_t hi,lo;
    float2 q = *(const float2*)(g_q + idx*2);
    split_pairh(q.x*scale, q.y*scale, hi, lo);
    g_qh[idx]=hi; g_ql[idx]=lo;
    float2 k = *(const float2*)(g_k + idx*2);
    g_kh[idx] = round_pairh(k.x, k.y);
    float2 v = *(const float2*)(g_v + idx*2);
    g_vh[idx] = round_pairh(v.x, v.y);
}

// =============== 2-term fp16 m16n8k16 grouped GEMM, cp.async pipelined =====
#define GS_TOK 0
#define GS_W   512
#define GS_A   1024
#define GS_ABUF 10240
#define GS_B   (GS_A + 4*GS_ABUF)      // 41984
#define GS_BBUF 8704
#define GS_TOTAL (GS_B + 2*GS_BBUF)    // 59392

template<int KTOT, int LDAW, int LDBW, int LDO, int QKV>
__global__ void __launch_bounds__(256) fp16_gemm_kernel(float* __restrict__ OutP){
    int e = blockIdx.z;
    int cnt = g_cnt[e];
    int m0 = blockIdx.x*128;
    if(m0>=cnt) return;
    int off = g_off[e];

    const uint32_t *Axh, *Axl, *Bh;
    float* Out; int n0;
    if(QKV){
        Axh = g_xh; Axl = g_xl;
        long woff = ((long)blockIdx.y*NE + e)*NC*(NH/2);
        Bh = g_wh + woff;
        Out = (blockIdx.y==0)? g_q : (blockIdx.y==1? g_k : g_v);
        n0 = 0;
    } else {
        Axh = g_oh; Axl = g_ol;
        long woff = (long)e*NH*(NC/2);
        Bh = g_oph + woff;
        Out = OutP;
        n0 = blockIdx.y*128;
    }
    int n0w = n0/2;

    extern __shared__ __align__(16) char smem[];
    uint32_t sb = smem_u32(smem);
    int*   stok = (int*)(smem + GS_TOK);
    float* sw   = (float*)(smem + GS_W);

    int tid=threadIdx.x, lane=tid&31, wid=tid>>5;
    int wr = wid>>2, wc = wid&3;

    if(tid<128){
        int m=m0+tid; int mm = m<cnt? m : cnt-1;
        stok[tid]=g_pair_tok[off+mm];
        sw[tid]= (m<cnt)? g_pair_w[off+mm] : 0.f;
    }
    __syncthreads();

    int ar = tid>>1, ahalf = tid&1;
    const uint32_t* ash = Axh + (long)stok[ar]*LDAW + ahalf*8;
    const uint32_t* asl = Axl + (long)stok[ar]*LDAW + ahalf*8;
    uint32_t adst = sb + GS_A + ar*80 + ahalf*32;
    int bk = tid>>3, bn = (tid&7)*8;
    const uint32_t* bsh = Bh + (long)bk*LDBW + n0w + bn;
    uint32_t bdst = sb + GS_B + bk*272 + bn*4;

    const int NCH = KTOT/32;

    int mid = lane>>3, l7 = lane&7;
    uint32_t aRel[4];
    #pragma unroll
    for(int mf=0;mf<4;mf++){
        int row = wr*64 + mf*16 + (mid&1)*8 + l7;
        aRel[mf] = row*80 + (mid>>1)*16;
    }
    uint32_t bRel[2];
    #pragma unroll
    for(int g=0;g<2;g++){
        int krow = (mid&1)*8 + l7;
        int ncol = wc*32 + g*16 + (mid>>1)*8;
        bRel[g] = krow*272 + ncol*2;
    }

    float acc[4][4][4];
    #pragma unroll
    for(int mf=0;mf<4;mf++)
        #pragma unroll
        for(int nf=0;nf<4;nf++)
            #pragma unroll
            for(int u=0;u<4;u++) acc[mf][nf][u]=0.f;

    {
        CP16(adst,               ash);
        CP16(adst+16,            ash+4);
        CP16(adst+GS_ABUF,       asl);
        CP16(adst+GS_ABUF+16,    asl+4);
        CP16(bdst,               bsh);
        CP16(bdst+16,            bsh+4);
        CP_COMMIT();
    }

    for(int c=0;c<NCH;c++){
        if(c+1<NCH){
            int st = (c+1)&1;
            uint32_t ad = adst + st*(2*GS_ABUF);
            uint32_t bd = bdst + st*GS_BBUF;
            const uint32_t* ash2 = ash + (c+1)*16;
            const uint32_t* asl2 = asl + (c+1)*16;
            const uint32_t* bsh2 = bsh + (long)(c+1)*32*LDBW;
            CP16(ad,            ash2);
            CP16(ad+16,         ash2+4);
            CP16(ad+GS_ABUF,    asl2);
            CP16(ad+GS_ABUF+16, asl2+4);
            CP16(bd,            bsh2);
            CP16(bd+16,         bsh2+4);
            CP_COMMIT();
            CP_WAIT(1);
        } else {
            CP_WAIT(0);
        }
        __syncthreads();

        uint32_t stA = sb + GS_A + (c&1)*(2*GS_ABUF);
        uint32_t stB = sb + GS_B + (c&1)*GS_BBUF;

        #pragma unroll
        for(int s=0;s<2;s++){
            uint32_t ahh[4][4], alo[4][4];
            #pragma unroll
            for(int mf=0;mf<4;mf++){
                LDM4(ahh[mf][0],ahh[mf][1],ahh[mf][2],ahh[mf][3], stA + aRel[mf] + s*32);
                LDM4(alo[mf][0],alo[mf][1],alo[mf][2],alo[mf][3], stA + GS_ABUF + aRel[mf] + s*32);
            }
            #pragma unroll
            for(int g=0;g<2;g++){
                uint32_t bh[4];
                LDM4T(bh[0],bh[1],bh[2],bh[3], stB + bRel[g] + s*4352);
                #pragma unroll
                for(int sub=0;sub<2;sub++){
                    #pragma unroll
                    for(int mf=0;mf<4;mf++){
                        float* C = acc[mf][g*2+sub];
                        mma16(C, ahh[mf][0],ahh[mf][1],ahh[mf][2],ahh[mf][3], bh[sub*2],bh[sub*2+1]);
                        mma16(C, alo[mf][0],alo[mf][1],alo[mf][2],alo[mf][3], bh[sub*2],bh[sub*2+1]);
                    }
                }
            }
        }
        __syncthreads();
    }

    #pragma unroll
    for(int mf=0;mf<4;mf++){
        int r0 = wr*64 + mf*16 + (lane>>2);
        int r1 = r0 + 8;
        float w0 = sw[r0], w1 = sw[r1];
        int live0 = (m0 + r0 < cnt), live1 = (m0 + r1 < cnt);
        long b0 = (long)stok[r0]*LDO + n0;
        long b1 = (long)stok[r1]*LDO + n0;
        #pragma unroll
        for(int nf=0;nf<4;nf++){
            int col = wc*32 + nf*8 + (lane&3)*2;
            if(live0){
                atomicAdd(&Out[b0 + col    ], acc[mf][nf][0]*w0);
                atomicAdd(&Out[b0 + col + 1], acc[mf][nf][1]*w0);
            }
            if(live1){
                atomicAdd(&Out[b1 + col    ], acc[mf][nf][2]*w1);
                atomicAdd(&Out[b1 + col + 1], acc[mf][nf][3]*w1);
            }
        }
    }
}

// ------------- flash attention, 32-row q-tiles, 2 CTAs/SM ------------------
// Q,P split hi/lo (A-side); K,V rounded single (B-side). Warps 2x4:
// S warp tile 16x16, PV warp tile 16x32. KV tiles stay 64 rows, double-buffered.
#define AQH 0
#define AQL 8704
#define AKV0 17408
#define AKV1 52224
#define AKVST 17408            // V offset within a KV stage
#define APH 87040
#define APL 91648
#define AREDM 96256            // 4 groups x 32 rows
#define AREDL 96768
#define AMROW 97280
#define ALROW 97408
#define AAROW 97536
#define ATTN_SMEM 97664

__global__ void __launch_bounds__(256) attn_tc_kernel(){
    extern __shared__ __align__(16) char smem[];
    uint32_t sb = smem_u32(smem);
    float* redm = (float*)(smem + AREDM);
    float* redl = (float*)(smem + AREDL);
    float* mrow = (float*)(smem + AMROW);
    float* lrow = (float*)(smem + ALROW);
    float* arow = (float*)(smem + AAROW);

    int b = blockIdx.y, qt = blockIdx.x;
    int tid = threadIdx.x, lane = tid&31, wid = tid>>5;
    int wr = wid>>2, wc = wid&3;
    long qbase = (long)b*NT + (long)qt*32;

    // load mappings: Q 32 rows (8 thr/row, 32B each); KV 64 rows (4 thr/row, 64B)
    int qlr = tid>>3, qlq = tid&7;
    uint32_t qldst = qlr*272 + qlq*32;
    int klr = tid>>2, klq = tid&3;
    uint32_t kldst = klr*272 + klq*64;

    {
        const uint32_t* qh = g_qh + (qbase+qlr)*64 + qlq*8;
        const uint32_t* ql = g_ql + (qbase+qlr)*64 + qlq*8;
        CP16(sb + AQH + qldst,      qh);
        CP16(sb + AQH + qldst + 16, qh + 4);
        CP16(sb + AQL + qldst,      ql);
        CP16(sb + AQL + qldst + 16, ql + 4);
        long kb = (long)b*NT;
        const uint32_t* kh = g_kh + (kb+klr)*64 + klq*16;
        const uint32_t* vh = g_vh + (kb+klr)*64 + klq*16;
        #pragma unroll
        for(int q=0;q<4;q++){
            CP16(sb + AKV0 +         kldst + q*16, kh + q*4);
            CP16(sb + AKV0 + AKVST + kldst + q*16, vh + q*4);
        }
        CP_COMMIT();
    }
    if(tid<32){ mrow[tid]=-INFINITY; lrow[tid]=0.f; }

    float oacc[4][4];
    #pragma unroll
    for(int nf=0;nf<4;nf++)
        #pragma unroll
        for(int u=0;u<4;u++) oacc[nf][u]=0.f;

    int r0 = wr*16 + (lane>>2), r1 = r0+8;   // rows 0..31

    int mid = lane>>3, l7 = lane&7;
    uint32_t qAddr, pAddr, kRel, vRel[2];
    {
        int row = wr*16 + (mid&1)*8 + l7;
        qAddr = sb + AQH + row*272 + (mid>>1)*16;
        pAddr = sb + APH + row*144 + (mid>>1)*16;
        int n = wc*16 + (mid>>1)*8 + l7;
        kRel = n*272 + (mid&1)*16;
        #pragma unroll
        for(int g=0;g<2;g++){
            int krow = (mid&1)*8 + l7;
            int ncol = wc*32 + g*16 + (mid>>1)*8;
            vRel[g] = krow*272 + ncol*2;
        }
    }

    for(int kt=0; kt<NT/64; kt++){
        if(kt+1 < NT/64){
            uint32_t base = sb + (((kt+1)&1) ? AKV1 : AKV0);
            long kb = (long)b*NT + (long)(kt+1)*64;
            const uint32_t* kh = g_kh + (kb+klr)*64 + klq*16;
            const uint32_t* vh = g_vh + (kb+klr)*64 + klq*16;
            #pragma unroll
            for(int q=0;q<4;q++){
                CP16(base +         kldst + q*16, kh + q*4);
                CP16(base + AKVST + kldst + q*16, vh + q*4);
            }
            CP_COMMIT();
            CP_WAIT(1);
        } else {
            CP_WAIT(0);
        }
        __syncthreads();

        uint32_t kvb = sb + ((kt&1) ? AKV1 : AKV0);
        uint32_t kH = kvb, vH = kvb + AKVST;

        // ---- S = Q K^T : warp tile 16x16 over S[32x64] ----
        float sacc[2][4];
        #pragma unroll
        for(int sub=0;sub<2;sub++)
            #pragma unroll
            for(int u=0;u<4;u++) sacc[sub][u]=0.f;

        #pragma unroll
        for(int s=0;s<8;s++){
            uint32_t qh[4], ql[4];
            LDM4(qh[0],qh[1],qh[2],qh[3], qAddr + s*32);
            LDM4(ql[0],ql[1],ql[2],ql[3], qAddr + (AQL-AQH) + s*32);
            uint32_t khf[4];
            LDM4(khf[0],khf[1],khf[2],khf[3], kH + kRel + s*32);
            #pragma unroll
            for(int sub=0;sub<2;sub++){
                float* C = sacc[sub];
                mma16(C, qh[0],qh[1],qh[2],qh[3], khf[sub*2],khf[sub*2+1]);
                mma16(C, ql[0],ql[1],ql[2],ql[3], khf[sub*2],khf[sub*2+1]);
            }
        }

        // ---- row max (4 wc groups x 32 rows) ----
        float pm0 = fmaxf(fmaxf(sacc[0][0],sacc[0][1]), fmaxf(sacc[1][0],sacc[1][1]));
        float pm1 = fmaxf(fmaxf(sacc[0][2],sacc[0][3]), fmaxf(sacc[1][2],sacc[1][3]));
        pm0 = fmaxf(pm0, __shfl_xor_sync(0xffffffffu, pm0, 1));
        pm0 = fmaxf(pm0, __shfl_xor_sync(0xffffffffu, pm0, 2));
        pm1 = fmaxf(pm1, __shfl_xor_sync(0xffffffffu, pm1, 1));
        pm1 = fmaxf(pm1, __shfl_xor_sync(0xffffffffu, pm1, 2));
        if((lane&3)==0){
            redm[wc*32 + r0] = pm0;
            redm[wc*32 + r1] = pm1;
        }
        __syncthreads();
        if(tid<32){
            float mo = mrow[tid];
            float mn = fmaxf(fmaxf(redm[tid], redm[32+tid]), fmaxf(redm[64+tid], redm[96+tid]));
            mn = fmaxf(mo, mn);
            arow[tid] = expf(mo - mn);
            mrow[tid] = mn;
        }
        __syncthreads();

        // ---- P = exp(S-m) -> split fp16 smem; partial sums; rescale oacc ---
        float mn0 = mrow[r0], mn1 = mrow[r1];
        float a0 = arow[r0], a1 = arow[r1];
        float rs0=0.f, rs1=0.f;
        #pragma unroll
        for(int sub=0;sub<2;sub++){
            int col = wc*16 + sub*8 + (lane&3)*2;
            float p0 = expf(sacc[sub][0]-mn0);
            float p1 = expf(sacc[sub][1]-mn0);
            float p2 = expf(sacc[sub][2]-mn1);
            float p3 = expf(sacc[sub][3]-mn1);
            rs0 += p0+p1; rs1 += p2+p3;
            uint32_t hi,lo;
            split_pairh(p0,p1,hi,lo);
            *(uint32_t*)(smem + APH + r0*144 + col*2) = hi;
            *(uint32_t*)(smem + APL + r0*144 + col*2) = lo;
            split_pairh(p2,p3,hi,lo);
            *(uint32_t*)(smem + APH + r1*144 + col*2) = hi;
            *(uint32_t*)(smem + APL + r1*144 + col*2) = lo;
        }
        rs0 += __shfl_xor_sync(0xffffffffu, rs0, 1);
        rs0 += __shfl_xor_sync(0xffffffffu, rs0, 2);
        rs1 += __shfl_xor_sync(0xffffffffu, rs1, 1);
        rs1 += __shfl_xor_sync(0xffffffffu, rs1, 2);
        if((lane&3)==0){
            redl[wc*32 + r0] = rs0;
            redl[wc*32 + r1] = rs1;
        }
        #pragma unroll
        for(int nf=0;nf<4;nf++){
            oacc[nf][0]*=a0; oacc[nf][1]*=a0;
            oacc[nf][2]*=a1; oacc[nf][3]*=a1;
        }
        __syncthreads();
        if(tid<32) lrow[tid] = lrow[tid]*arow[tid] + redl[tid] + redl[32+tid] + redl[64+tid] + redl[96+tid];

        // ---- O += P V : warp tile 16x32 over O[32x128] ----
        #pragma unroll
        for(int s=0;s<4;s++){
            uint32_t ph[4], pl[4];
            LDM4(ph[0],ph[1],ph[2],ph[3], pAddr + s*32);
            LDM4(pl[0],pl[1],pl[2],pl[3], pAddr + (APL-APH) + s*32);
            #pragma unroll
            for(int g=0;g<2;g++){
                uint32_t vhf[4];
                LDM4T(vhf[0],vhf[1],vhf[2],vhf[3], vH + vRel[g] + s*4352);
                #pragma unroll
                for(int sub=0;sub<2;sub++){
                    float* C = oacc[g*2+sub];
                    mma16(C, ph[0],ph[1],ph[2],ph[3], vhf[sub*2],vhf[sub*2+1]);
                    mma16(C, pl[0],pl[1],pl[2],pl[3], vhf[sub*2],vhf[sub*2+1]);
                }
            }
        }
        __syncthreads();
    }

    // ---- epilogue: normalize + store packed fp16 hi/lo --------------------
    float il0 = 1.f/lrow[r0], il1 = 1.f/lrow[r1];
    #pragma unroll
    for(int nf=0;nf<4;nf++){
        int colw = wc*16 + nf*4 + (lane&3);
        uint32_t hi,lo;
        split_pairh(oacc[nf][0]*il0, oacc[nf][1]*il0, hi, lo);
        g_oh[(qbase+r0)*64 + colw] = hi;
        g_ol[(qbase+r0)*64 + colw] = lo;
        split_pairh(oacc[nf][2]*il1, oacc[nf][3]*il1, hi, lo);
        g_oh[(qbase+r1)*64 + colw] = hi;
        g_ol[(qbase+r1)*64 + colw] = lo;
    }
}

// ---------------------------------------------------------------------------
extern "C" void kernel_launch(void* const* d_in, const int* in_sizes, int n_in,
                              void* d_out, int out_size){
    (void)in_sizes; (void)n_in; (void)out_size;
    const float* hs   = (const float*)d_in[0];
    const float* sim  = (const float*)d_in[1];
    const float* gates= (const float*)d_in[2];
    const float* qp   = (const float*)d_in[3];
    const float* kp   = (const float*)d_in[4];
    const float* vp   = (const float*)d_in[5];
    const float* op   = (const float*)d_in[6];
    float* out = (float*)d_out;

    cudaFuncSetAttribute(attn_tc_kernel, cudaFuncAttributeMaxDynamicSharedMemorySize, ATTN_SMEM);
    cudaFuncSetAttribute(fp16_gemm_kernel<NC,512,64,NH,1>, cudaFuncAttributeMaxDynamicSharedMemorySize, GS_TOTAL);
    cudaFuncSetAttribute(fp16_gemm_kernel<NH,64,512,NC,0>, cudaFuncAttributeMaxDynamicSharedMemorySize, GS_TOTAL);

    zero_kernel<<<2048,256>>>(out);
    prep_kernel<<<NE,256>>>(sim,gates);
    conv_w_kernel<<<4096,256>>>(qp,kp,vp,op);
    pack_x_kernel<<<2048,256>>>(hs);
    gate4_kernel<<<dim3(NN/64,4),256>>>(hs);
    gatefin_kernel<<<NN/256,256>>>();
    scan_kernel<<<1,32>>>();
    pairfill_kernel<<<NN/256,256>>>();
    fp16_gemm_kernel<NC,512,64,NH,1><<<dim3(64,3,16),256,GS_TOTAL>>>(nullptr);
    conv_qkv_kernel<<<2048,256>>>();
    attn_tc_kernel<<<dim3(NT/32,NB),256,ATTN_SMEM>>>();
    fp16_gemm_kernel<NH,64,512,NC,0><<<dim3(64,8,16),256,GS_TOTAL>>>(out);
}

// round 15
// speedup vs baseline: 1.1097x; 1.1097x over previous
#include <cuda_runtime.h>
#include <cuda_fp16.h>
#include <math.h>
#include <cstdint>

#define NB 4
#define NT 2048
#define NC 1024
#define NH 128
#define NE 16
#define NN (NB*NT)   // 8192 tokens

// ---------------- scratch (static device allocations; no runtime alloc) ----
static __device__ float g_sn[NC*NE];
static __device__ float g_sig[NE];
static __device__ int   g_nact[NN];
static __device__ unsigned char g_tok_e[NN*NE];
static __device__ float g_tok_w[NN*NE];
static __device__ int   g_cnt[NE];
static __device__ int   g_off[NE];
static __device__ int   g_cur[NE];
static __device__ int   g_pair_tok[NN*NE];
static __device__ float g_pair_w[NN*NE];
static __device__ float g_q[NN*NH];
static __device__ float g_k[NN*NH];
static __device__ float g_v[NN*NH];
static __device__ float g_pdot[4*NN*NE];   // split-K gating partials
static __device__ float g_pssq[4*NN];
// split-KV attention partials
static __device__ float g_po[2L*NN*NH];
static __device__ float g_pm[2*NN];
static __device__ float g_pl[2*NN];

// packed fp16x2 operand arrays (A-side split hi/lo; B-side rounded single)
static __device__ uint32_t g_xh[NN*NC/2],  g_xl[NN*NC/2];        // X (A, split)
static __device__ uint32_t g_wh[3*NE*NC*NH/2];                   // qkv proj (B)
static __device__ uint32_t g_oph[NE*NH*NC/2];                    // o proj (B)
static __device__ uint32_t g_qh[NN*NH/2], g_ql[NN*NH/2];         // Q (A, split)
static __device__ uint32_t g_kh[NN*NH/2];                        // K (B)
static __device__ uint32_t g_vh[NN*NH/2];                        // V (B)
static __device__ uint32_t g_oh[NN*NH/2], g_ol[NN*NH/2];         // attn out (A, split)

// ================= helpers ==================================================
__device__ __forceinline__ uint32_t smem_u32(const void* p){
    uint32_t a;
    asm("{ .reg .u64 t; cvta.to.shared.u64 t, %1; cvt.u32.u64 %0, t; }" : "=r"(a) : "l"(p));
    return a;
}
__device__ __forceinline__ void split_pairh(float x, float y, uint32_t& hi, uint32_t& lo){
    __half2 h = __floats2half2_rn(x, y);
    float rx = x - __low2float(h);
    float ry = y - __high2float(h);
    __half2 l = __floats2half2_rn(rx, ry);
    hi = *(uint32_t*)&h;
    lo = *(uint32_t*)&l;
}
__device__ __forceinline__ uint32_t round_pairh(float x, float y){
    __half2 h = __floats2half2_rn(x, y);
    return *(uint32_t*)&h;
}
#define CP16(dst,src) asm volatile("cp.async.ca.shared.global [%0], [%1], 16;" :: "r"(dst), "l"(src))
#define CP_COMMIT()   asm volatile("cp.async.commit_group;" ::: "memory")
#define CP_WAIT(n)    asm volatile("cp.async.wait_group %0;" :: "n"(n) : "memory")
#define LDM4(r0,r1,r2,r3,addr) \
    asm volatile("ldmatrix.sync.aligned.m8n8.x4.shared.b16 {%0,%1,%2,%3}, [%4];" \
        : "=r"(r0),"=r"(r1),"=r"(r2),"=r"(r3) : "r"(addr))
#define LDM4T(r0,r1,r2,r3,addr) \
    asm volatile("ldmatrix.sync.aligned.m8n8.x4.trans.shared.b16 {%0,%1,%2,%3}, [%4];" \
        : "=r"(r0),"=r"(r1),"=r"(r2),"=r"(r3) : "r"(addr))
__device__ __forceinline__ void mma16(float c[4],
        uint32_t a0,uint32_t a1,uint32_t a2,uint32_t a3,
        uint32_t b0,uint32_t b1){
    asm volatile("mma.sync.aligned.m16n8k16.row.col.f32.f16.f16.f32 "
        "{%0,%1,%2,%3}, {%4,%5,%6,%7}, {%8,%9}, {%0,%1,%2,%3};"
        : "+f"(c[0]),"+f"(c[1]),"+f"(c[2]),"+f"(c[3])
        : "r"(a0),"r"(a1),"r"(a2),"r"(a3),"r"(b0),"r"(b1));
}

// ---------------- zero / init ----------------
__global__ void zero_kernel(float* __restrict__ out){
    long i = (long)blockIdx.x*blockDim.x + threadIdx.x;
    long stride = (long)gridDim.x*blockDim.x;
    for(long j=i;j<(long)NN*NH;j+=stride){ g_q[j]=0.f; g_k[j]=0.f; g_v[j]=0.f; }
    for(long j=i;j<(long)NN*NC;j+=stride) out[j]=0.f;
    if(i<NE) g_cnt[(int)i]=0;
}

// ---------------- sim-matrix column normalization + sigmoid(gates) ---------
__global__ void prep_kernel(const float* __restrict__ sim, const float* __restrict__ gates){
    int e = blockIdx.x;
    __shared__ float red[256];
    float ss=0.f;
    for(int c=threadIdx.x;c<NC;c+=256){ float v=sim[c*NE+e]; ss+=v*v; }
    red[threadIdx.x]=ss; __syncthreads();
    for(int s=128;s>0;s>>=1){ if(threadIdx.x<s) red[threadIdx.x]+=red[threadIdx.x+s]; __syncthreads(); }
    float inv = 1.f/fmaxf(sqrtf(red[0]),1e-12f);
    for(int c=threadIdx.x;c<NC;c+=256) g_sn[c*NE+e]=sim[c*NE+e]*inv;
    if(threadIdx.x==0) g_sig[e]=1.f/(1.f+expf(-gates[e]));
}

// ---------------- weight pre-pack (fp16 rounded, B-side only) --------------
__global__ void conv_w_kernel(const float* __restrict__ qp, const float* __restrict__ kp,
                              const float* __restrict__ vp, const float* __restrict__ op){
    const long NW_QKV = (long)3*NE*NC*NH/2;
    const long NW_OP  = (long)NE*NH*NC/2;
    const long PERP   = (long)NE*NC*NH/2;
    long stride = (long)gridDim.x*blockDim.x;
    for(long idx = (long)blockIdx.x*blockDim.x + threadIdx.x; idx < NW_QKV+NW_OP; idx += stride){
        if(idx < NW_QKV){
            long p = idx / PERP;
            long r = idx - p*PERP;
            const float* src = (p==0? qp : (p==1? kp : vp)) + r*2;
            float2 v = *(const float2*)src;
            g_wh[idx] = round_pairh(v.x,v.y);
        } else {
            long r = idx - NW_QKV;
            float2 v = *(const float2*)(op + r*2);
            g_oph[r] = round_pairh(v.x,v.y);
        }
    }
}

// ---------------- X pack: fp32 -> fp16 hi/lo (pure streaming) --------------
__global__ void __launch_bounds__(256) pack_x_kernel(const float* __restrict__ X){
    const long NW = (long)NN*NC/4;
    long stride = (long)gridDim.x*blockDim.x;
    for(long idx = (long)blockIdx.x*blockDim.x + threadIdx.x; idx < NW; idx += stride){
        float4 v = *(const float4*)(X + idx*4);
        uint32_t h0,l0,h1,l1;
        split_pairh(v.x,v.y,h0,l0);
        split_pairh(v.z,v.w,h1,l1);
        *(uint2*)(g_xh + idx*2) = make_uint2(h0,h1);
        *(uint2*)(g_xl + idx*2) = make_uint2(l0,l1);
    }
}

// ---------------- gating v4: split-K, loads batched, no stores in loop -----
#define GT3_ESTR 68
#define GT3_SECT 1096

__global__ void __launch_bounds__(256) gate4_kernel(const float* __restrict__ X){
    __shared__ float sns[4*GT3_SECT];
    int tid = threadIdx.x;
    int kz = blockIdx.y;
    for(int i=tid; i<16*256; i+=256){
        int e = i>>8, c = i&255;
        sns[(c>>6)*GT3_SECT + e*GT3_ESTR + (c&63)] = g_sn[(kz*256 + c)*NE + e];
    }
    __syncthreads();

    int part = tid&3, tl = tid>>2;
    int token = blockIdx.x*64 + tl;
    const float4* x4 = (const float4*)(X + (long)token*NC + kz*256 + part*64);
    const float* snp = sns + part*GT3_SECT;

    float ssq = 0.f, dot[NE];
    #pragma unroll
    for(int e=0;e<NE;e++) dot[e]=0.f;

    #pragma unroll
    for(int h=0; h<2; h++){
        float4 xv[8];
        #pragma unroll
        for(int i=0;i<8;i++) xv[i] = x4[h*8 + i];
        #pragma unroll
        for(int i=0;i<8;i++){
            float4 v = xv[i];
            ssq += v.x*v.x + v.y*v.y + v.z*v.z + v.w*v.w;
            const float* sp = snp + (h*8+i)*4;
            #pragma unroll
            for(int e=0;e<NE;e++){
                float4 s = *(const float4*)(sp + e*GT3_ESTR);
                dot[e] += v.x*s.x + v.y*s.y + v.z*s.z + v.w*s.w;
            }
        }
    }
    #pragma unroll
    for(int off=1; off<4; off<<=1){
        ssq += __shfl_xor_sync(0xffffffffu, ssq, off);
        #pragma unroll
        for(int e=0;e<NE;e++) dot[e] += __shfl_xor_sync(0xffffffffu, dot[e], off);
    }
    if(part==0){
        g_pssq[kz*NN + token] = ssq;
        float* pd = g_pdot + ((long)kz*NN + token)*NE;
        #pragma unroll
        for(int e4=0;e4<4;e4++)
            *(float4*)(pd + e4*4) = make_float4(dot[e4*4],dot[e4*4+1],dot[e4*4+2],dot[e4*4+3]);
    }
}

// ---------------- gating finalize ------------------------------------------
__global__ void __launch_bounds__(256) gatefin_kernel(){
    int token = blockIdx.x*256 + threadIdx.x;
    if(token >= NN) return;
    float ssq = 0.f, dot[NE];
    #pragma unroll
    for(int e=0;e<NE;e++) dot[e]=0.f;
    #pragma unroll
    for(int kz=0;kz<4;kz++){
        ssq += g_pssq[kz*NN + token];
        const float* pd = g_pdot + ((long)kz*NN + token)*NE;
        #pragma unroll
        for(int e4=0;e4<4;e4++){
            float4 d = *(const float4*)(pd + e4*4);
            dot[e4*4+0]+=d.x; dot[e4*4+1]+=d.y; dot[e4*4+2]+=d.z; dot[e4*4+3]+=d.w;
        }
    }
    float inv = 1.f/fmaxf(sqrtf(ssq),1e-12f);
    float logit[NE];
    #pragma unroll
    for(int e=0;e<NE;e++) logit[e] = dot[e]*inv - g_sig[e];
    int act[NE]; int na=0;
    for(int e=0;e<NE;e++) if(logit[e]>0.f) act[na++]=e;
    if(na==0){
        int i1=0;
        for(int e=1;e<NE;e++) if(logit[e]>logit[i1]) i1=e;
        int i2=-1;
        for(int e=0;e<NE;e++) if(e!=i1 && (i2<0 || logit[e]>logit[i2])) i2=e;
        int a = i1<i2? i1:i2; int b2 = i1<i2? i2:i1;
        act[0]=a; act[1]=b2; na=2;
    }
    float vals[NE]; float mx=-1e30f;
    for(int k=0;k<na;k++){ vals[k]=fmaxf(logit[act[k]],0.f); mx=fmaxf(mx,vals[k]); }
    float sum=0.f;
    for(int k=0;k<na;k++){ vals[k]=expf(vals[k]-mx); sum+=vals[k]; }
    float isum = 1.f/sum;
    g_nact[token]=na;
    for(int k=0;k<na;k++){
        g_tok_e[token*NE+k]=(unsigned char)act[k];
        g_tok_w[token*NE+k]=vals[k]*isum;
        atomicAdd(&g_cnt[act[k]],1);
    }
}

__global__ void scan_kernel(){
    if(threadIdx.x==0){
        int o=0;
        for(int e=0;e<NE;e++){ g_off[e]=o; o+=g_cnt[e]; }
    }
    if(threadIdx.x<NE) g_cur[threadIdx.x]=0;
}

__global__ void pairfill_kernel(){
    int n = blockIdx.x*blockDim.x + threadIdx.x;
    if(n>=NN) return;
    int na=g_nact[n];
    for(int k=0;k<na;k++){
        int e=g_tok_e[n*NE+k];
        int s=atomicAdd(&g_cur[e],1);
        int p=g_off[e]+s;
        g_pair_tok[p]=n;
        g_pair_w[p]=g_tok_w[n*NE+k];
    }
}

// ---------------- q/k/v fp32 -> fp16 (Q split+scaled; K,V rounded) ---------
__global__ void conv_qkv_kernel(){
    const float scale = 0.0883883476483184f;  // 1/sqrt(128)
    long idx = (long)blockIdx.x*blockDim.x + threadIdx.x;
    if(idx >= (long)NN*NH/2) return;
    uint32_t hi,lo;
    float2 q = *(const float2*)(g_q + idx*2);
    split_pairh(q.x*scale, q.y*scale, hi, lo);
    g_qh[idx]=hi; g_ql[idx]=lo;
    float2 k = *(const float2*)(g_k + idx*2);
    g_kh[idx] = round_pairh(k.x, k.y);
    float2 v = *(const float2*)(g_v + idx*2);
    g_vh[idx] = round_pairh(v.x, v.y);
}

// =============== 2-term fp16 m16n8k16 grouped GEMM, cp.async pipelined =====
#define GS_TOK 0
#define GS_W   512
#define GS_A   1024
#define GS_ABUF 10240
#define GS_B   (GS_A + 4*GS_ABUF)      // 41984
#define GS_BBUF 8704
#define GS_TOTAL (GS_B + 2*GS_BBUF)    // 59392

template<int KTOT, int LDAW, int LDBW, int LDO, int QKV>
__global__ void __launch_bounds__(256) fp16_gemm_kernel(float* __restrict__ OutP){
    int e = blockIdx.z;
    int cnt = g_cnt[e];
    int m0 = blockIdx.x*128;
    if(m0>=cnt) return;
    int off = g_off[e];

    const uint32_t *Axh, *Axl, *Bh;
    float* Out; int n0;
    if(QKV){
        Axh = g_xh; Axl = g_xl;
        long woff = ((long)blockIdx.y*NE + e)*NC*(NH/2);
        Bh = g_wh + woff;
        Out = (blockIdx.y==0)? g_q : (blockIdx.y==1? g_k : g_v);
        n0 = 0;
    } else {
        Axh = g_oh; Axl = g_ol;
        long woff = (long)e*NH*(NC/2);
        Bh = g_oph + woff;
        Out = OutP;
        n0 = blockIdx.y*128;
    }
    int n0w = n0/2;

    extern __shared__ __align__(16) char smem[];
    uint32_t sb = smem_u32(smem);
    int*   stok = (int*)(smem + GS_TOK);
    float* sw   = (float*)(smem + GS_W);

    int tid=threadIdx.x, lane=tid&31, wid=tid>>5;
    int wr = wid>>2, wc = wid&3;

    if(tid<128){
        int m=m0+tid; int mm = m<cnt? m : cnt-1;
        stok[tid]=g_pair_tok[off+mm];
        sw[tid]= (m<cnt)? g_pair_w[off+mm] : 0.f;
    }
    __syncthreads();

    int ar = tid>>1, ahalf = tid&1;
    const uint32_t* ash = Axh + (long)stok[ar]*LDAW + ahalf*8;
    const uint32_t* asl = Axl + (long)stok[ar]*LDAW + ahalf*8;
    uint32_t adst = sb + GS_A + ar*80 + ahalf*32;
    int bk = tid>>3, bn = (tid&7)*8;
    const uint32_t* bsh = Bh + (long)bk*LDBW + n0w + bn;
    uint32_t bdst = sb + GS_B + bk*272 + bn*4;

    const int NCH = KTOT/32;

    int mid = lane>>3, l7 = lane&7;
    uint32_t aRel[4];
    #pragma unroll
    for(int mf=0;mf<4;mf++){
        int row = wr*64 + mf*16 + (mid&1)*8 + l7;
        aRel[mf] = row*80 + (mid>>1)*16;
    }
    uint32_t bRel[2];
    #pragma unroll
    for(int g=0;g<2;g++){
        int krow = (mid&1)*8 + l7;
        int ncol = wc*32 + g*16 + (mid>>1)*8;
        bRel[g] = krow*272 + ncol*2;
    }

    float acc[4][4][4];
    #pragma unroll
    for(int mf=0;mf<4;mf++)
        #pragma unroll
        for(int nf=0;nf<4;nf++)
            #pragma unroll
            for(int u=0;u<4;u++) acc[mf][nf][u]=0.f;

    {
        CP16(adst,               ash);
        CP16(adst+16,            ash+4);
        CP16(adst+GS_ABUF,       asl);
        CP16(adst+GS_ABUF+16,    asl+4);
        CP16(bdst,               bsh);
        CP16(bdst+16,            bsh+4);
        CP_COMMIT();
    }

    for(int c=0;c<NCH;c++){
        if(c+1<NCH){
            int st = (c+1)&1;
            uint32_t ad = adst + st*(2*GS_ABUF);
            uint32_t bd = bdst + st*GS_BBUF;
            const uint32_t* ash2 = ash + (c+1)*16;
            const uint32_t* asl2 = asl + (c+1)*16;
            const uint32_t* bsh2 = bsh + (long)(c+1)*32*LDBW;
            CP16(ad,            ash2);
            CP16(ad+16,         ash2+4);
            CP16(ad+GS_ABUF,    asl2);
            CP16(ad+GS_ABUF+16, asl2+4);
            CP16(bd,            bsh2);
            CP16(bd+16,         bsh2+4);
            CP_COMMIT();
            CP_WAIT(1);
        } else {
            CP_WAIT(0);
        }
        __syncthreads();

        uint32_t stA = sb + GS_A + (c&1)*(2*GS_ABUF);
        uint32_t stB = sb + GS_B + (c&1)*GS_BBUF;

        #pragma unroll
        for(int s=0;s<2;s++){
            uint32_t ahh[4][4], alo[4][4];
            #pragma unroll
            for(int mf=0;mf<4;mf++){
                LDM4(ahh[mf][0],ahh[mf][1],ahh[mf][2],ahh[mf][3], stA + aRel[mf] + s*32);
                LDM4(alo[mf][0],alo[mf][1],alo[mf][2],alo[mf][3], stA + GS_ABUF + aRel[mf] + s*32);
            }
            #pragma unroll
            for(int g=0;g<2;g++){
                uint32_t bh[4];
                LDM4T(bh[0],bh[1],bh[2],bh[3], stB + bRel[g] + s*4352);
                #pragma unroll
                for(int sub=0;sub<2;sub++){
                    #pragma unroll
                    for(int mf=0;mf<4;mf++){
                        float* C = acc[mf][g*2+sub];
                        mma16(C, ahh[mf][0],ahh[mf][1],ahh[mf][2],ahh[mf][3], bh[sub*2],bh[sub*2+1]);
                        mma16(C, alo[mf][0],alo[mf][1],alo[mf][2],alo[mf][3], bh[sub*2],bh[sub*2+1]);
                    }
                }
            }
        }
        __syncthreads();
    }

    #pragma unroll
    for(int mf=0;mf<4;mf++){
        int r0 = wr*64 + mf*16 + (lane>>2);
        int r1 = r0 + 8;
        float w0 = sw[r0], w1 = sw[r1];
        int live0 = (m0 + r0 < cnt), live1 = (m0 + r1 < cnt);
        long b0 = (long)stok[r0]*LDO + n0;
        long b1 = (long)stok[r1]*LDO + n0;
        #pragma unroll
        for(int nf=0;nf<4;nf++){
            int col = wc*32 + nf*8 + (lane&3)*2;
            if(live0){
                atomicAdd(&Out[b0 + col    ], acc[mf][nf][0]*w0);
                atomicAdd(&Out[b0 + col + 1], acc[mf][nf][1]*w0);
            }
            if(live1){
                atomicAdd(&Out[b1 + col    ], acc[mf][nf][2]*w1);
                atomicAdd(&Out[b1 + col + 1], acc[mf][nf][3]*w1);
            }
        }
    }
}

// ------------- flash attention, split-KV (2 halves), 64-row q-tiles --------
// Q,P split hi/lo (A-side); K,V rounded single (B-side). Single KV buffer,
// 89.9KB smem -> 2 CTAs/SM; 256 CTAs. Emits unnormalized O + (m,l) partials.
#define AQH 0
#define AQL 17408
#define AKV 34816
#define AKVST 17408            // V offset within KV buffer
#define APH 69632
#define APL 78848
#define AREDM 88064
#define AREDL 88576
#define AMROW 89088
#define ALROW 89344
#define AAROW 89600
#define ATTN_SMEM 89856

__global__ void __launch_bounds__(256,2) attn_tc_kernel(){
    extern __shared__ __align__(16) char smem[];
    uint32_t sb = smem_u32(smem);
    float* redm = (float*)(smem + AREDM);
    float* redl = (float*)(smem + AREDL);
    float* mrow = (float*)(smem + AMROW);
    float* lrow = (float*)(smem + ALROW);
    float* arow = (float*)(smem + AAROW);

    int b = blockIdx.y, qt = blockIdx.x;
    int half = blockIdx.z;
    long hoff = (long)half*NN;
    int tid = threadIdx.x, lane = tid&31, wid = tid>>5;
    int wr = wid>>1, wc = wid&1;
    long qbase = (long)b*NT + (long)qt*64;

    int lr = tid>>2, lq = tid&3;
    uint32_t ldst = lr*272 + lq*64;

    {
        const uint32_t* qh = g_qh + (qbase+lr)*64 + lq*16;
        const uint32_t* ql = g_ql + (qbase+lr)*64 + lq*16;
        #pragma unroll
        for(int q=0;q<4;q++){
            CP16(sb + AQH + ldst + q*16, qh + q*4);
            CP16(sb + AQL + ldst + q*16, ql + q*4);
        }
        long kb = (long)b*NT + (long)half*16*64;
        const uint32_t* kh = g_kh + (kb+lr)*64 + lq*16;
        const uint32_t* vh = g_vh + (kb+lr)*64 + lq*16;
        #pragma unroll
        for(int q=0;q<4;q++){
            CP16(sb + AKV +         ldst + q*16, kh + q*4);
            CP16(sb + AKV + AKVST + ldst + q*16, vh + q*4);
        }
        CP_COMMIT();
    }
    if(tid<64){ mrow[tid]=-INFINITY; lrow[tid]=0.f; }

    float oacc[8][4];
    #pragma unroll
    for(int nf=0;nf<8;nf++)
        #pragma unroll
        for(int u=0;u<4;u++) oacc[nf][u]=0.f;

    int r0 = wr*16 + (lane>>2), r1 = r0+8;

    int mid = lane>>3, l7 = lane&7;
    uint32_t qAddr, pAddr, kRel[2], vRel[4];
    {
        int row = wr*16 + (mid&1)*8 + l7;
        qAddr = sb + AQH + row*272 + (mid>>1)*16;
        pAddr = sb + APH + row*144 + (mid>>1)*16;
        #pragma unroll
        for(int g=0;g<2;g++){
            int n = wc*32 + g*16 + (mid>>1)*8 + l7;
            kRel[g] = n*272 + (mid&1)*16;
        }
        #pragma unroll
        for(int g=0;g<4;g++){
            int krow = (mid&1)*8 + l7;
            int ncol = wc*64 + g*16 + (mid>>1)*8;
            vRel[g] = krow*272 + ncol*2;
        }
    }

    for(int kt=0; kt<16; kt++){
        CP_WAIT(0);
        __syncthreads();

        uint32_t kH = sb + AKV, vH = sb + AKV + AKVST;

        float sacc[4][4];
        #pragma unroll
        for(int nf=0;nf<4;nf++)
            #pragma unroll
            for(int u=0;u<4;u++) sacc[nf][u]=0.f;

        #pragma unroll
        for(int s=0;s<8;s++){
            uint32_t qh[4], ql[4];
            LDM4(qh[0],qh[1],qh[2],qh[3], qAddr + s*32);
            LDM4(ql[0],ql[1],ql[2],ql[3], qAddr + (AQL-AQH) + s*32);
            #pragma unroll
            for(int g=0;g<2;g++){
                uint32_t khf[4];
                LDM4(khf[0],khf[1],khf[2],khf[3], kH + kRel[g] + s*32);
                #pragma unroll
                for(int sub=0;sub<2;sub++){
                    float* C = sacc[g*2+sub];
                    mma16(C, qh[0],qh[1],qh[2],qh[3], khf[sub*2],khf[sub*2+1]);
                    mma16(C, ql[0],ql[1],ql[2],ql[3], khf[sub*2],khf[sub*2+1]);
                }
            }
        }

        float pm0 = fmaxf(fmaxf(sacc[0][0],sacc[0][1]), fmaxf(sacc[1][0],sacc[1][1]));
        pm0 = fmaxf(pm0, fmaxf(fmaxf(sacc[2][0],sacc[2][1]), fmaxf(sacc[3][0],sacc[3][1])));
        float pm1 = fmaxf(fmaxf(sacc[0][2],sacc[0][3]), fmaxf(sacc[1][2],sacc[1][3]));
        pm1 = fmaxf(pm1, fmaxf(fmaxf(sacc[2][2],sacc[2][3]), fmaxf(sacc[3][2],sacc[3][3])));
        pm0 = fmaxf(pm0, __shfl_xor_sync(0xffffffffu, pm0, 1));
        pm0 = fmaxf(pm0, __shfl_xor_sync(0xffffffffu, pm0, 2));
        pm1 = fmaxf(pm1, __shfl_xor_sync(0xffffffffu, pm1, 1));
        pm1 = fmaxf(pm1, __shfl_xor_sync(0xffffffffu, pm1, 2));
        if((lane&3)==0){
            redm[wc*64 + r0] = pm0;
            redm[wc*64 + r1] = pm1;
        }
        __syncthreads();
        if(tid<64){
            float mo = mrow[tid];
            float mn = fmaxf(mo, fmaxf(redm[tid], redm[64+tid]));
            arow[tid] = expf(mo - mn);
            mrow[tid] = mn;
        }
        __syncthreads();

        float mn0 = mrow[r0], mn1 = mrow[r1];
        float a0 = arow[r0], a1 = arow[r1];
        float rs0=0.f, rs1=0.f;
        #pragma unroll
        for(int nf=0;nf<4;nf++){
            int col = wc*32 + nf*8 + (lane&3)*2;
            float p0 = expf(sacc[nf][0]-mn0);
            float p1 = expf(sacc[nf][1]-mn0);
            float p2 = expf(sacc[nf][2]-mn1);
            float p3 = expf(sacc[nf][3]-mn1);
            rs0 += p0+p1; rs1 += p2+p3;
            uint32_t hi,lo;
            split_pairh(p0,p1,hi,lo);
            *(uint32_t*)(smem + APH + r0*144 + col*2) = hi;
            *(uint32_t*)(smem + APL + r0*144 + col*2) = lo;
            split_pairh(p2,p3,hi,lo);
            *(uint32_t*)(smem + APH + r1*144 + col*2) = hi;
            *(uint32_t*)(smem + APL + r1*144 + col*2) = lo;
        }
        rs0 += __shfl_xor_sync(0xffffffffu, rs0, 1);
        rs0 += __shfl_xor_sync(0xffffffffu, rs0, 2);
        rs1 += __shfl_xor_sync(0xffffffffu, rs1, 1);
        rs1 += __shfl_xor_sync(0xffffffffu, rs1, 2);
        if((lane&3)==0){
            redl[wc*64 + r0] = rs0;
            redl[wc*64 + r1] = rs1;
        }
        #pragma unroll
        for(int nf=0;nf<8;nf++){
            oacc[nf][0]*=a0; oacc[nf][1]*=a0;
            oacc[nf][2]*=a1; oacc[nf][3]*=a1;
        }
        __syncthreads();
        if(tid<64) lrow[tid] = lrow[tid]*arow[tid] + redl[tid] + redl[64+tid];

        #pragma unroll
        for(int s=0;s<4;s++){
            uint32_t ph[4], pl[4];
            LDM4(ph[0],ph[1],ph[2],ph[3], pAddr + s*32);
            LDM4(pl[0],pl[1],pl[2],pl[3], pAddr + (APL-APH) + s*32);
            #pragma unroll
            for(int g=0;g<4;g++){
                uint32_t vhf[4];
                LDM4T(vhf[0],vhf[1],vhf[2],vhf[3], vH + vRel[g] + s*4352);
                #pragma unroll
                for(int sub=0;sub<2;sub++){
                    float* C = oacc[g*2+sub];
                    mma16(C, ph[0],ph[1],ph[2],ph[3], vhf[sub*2],vhf[sub*2+1]);
                    mma16(C, pl[0],pl[1],pl[2],pl[3], vhf[sub*2],vhf[sub*2+1]);
                }
            }
        }
        __syncthreads();

        if(kt+1 < 16){
            long kb = (long)b*NT + (long)(half*16 + kt+1)*64;
            const uint32_t* kh = g_kh + (kb+lr)*64 + lq*16;
            const uint32_t* vh = g_vh + (kb+lr)*64 + lq*16;
            #pragma unroll
            for(int q=0;q<4;q++){
                CP16(sb + AKV +         ldst + q*16, kh + q*4);
                CP16(sb + AKV + AKVST + ldst + q*16, vh + q*4);
            }
            CP_COMMIT();
        }
    }

    // ---- epilogue: store unnormalized O + (m,l) partials ------------------
    #pragma unroll
    for(int nf=0;nf<8;nf++){
        int col = wc*64 + nf*8 + (lane&3)*2;
        g_po[(hoff+qbase+r0)*NH + col    ] = oacc[nf][0];
        g_po[(hoff+qbase+r0)*NH + col + 1] = oacc[nf][1];
        g_po[(hoff+qbase+r1)*NH + col    ] = oacc[nf][2];
        g_po[(hoff+qbase+r1)*NH + col + 1] = oacc[nf][3];
    }
    if(tid<64){
        g_pm[hoff + qbase + tid] = mrow[tid];
        g_pl[hoff + qbase + tid] = lrow[tid];
    }
}

// ------------- attention combine: merge 2 KV halves, pack fp16 hi/lo -------
__global__ void __launch_bounds__(256) attnfin_kernel(){
    long idx = (long)blockIdx.x*256 + threadIdx.x;   // < NN*32
    int row = (int)(idx>>5), q4 = ((int)idx&31)*4;
    float m1=g_pm[row], m2=g_pm[NN+row];
    float l1=g_pl[row], l2=g_pl[NN+row];
    float m = fmaxf(m1,m2);
    float w1 = expf(m1-m), w2 = expf(m2-m);
    float inv = 1.f/(w1*l1 + w2*l2);
    float4 a = *(const float4*)(g_po + (long)row*NH + q4);
    float4 c = *(const float4*)(g_po + (long)(NN+row)*NH + q4);
    float c0=(w1*a.x+w2*c.x)*inv, c1=(w1*a.y+w2*c.y)*inv;
    float c2=(w1*a.z+w2*c.z)*inv, c3=(w1*a.w+w2*c.w)*inv;
    uint32_t hi,lo;
    split_pairh(c0,c1,hi,lo);
    g_oh[(long)row*64 + (q4>>1)    ] = hi;  g_ol[(long)row*64 + (q4>>1)    ] = lo;
    split_pairh(c2,c3,hi,lo);
    g_oh[(long)row*64 + (q4>>1) + 1] = hi;  g_ol[(long)row*64 + (q4>>1) + 1] = lo;
}

// ---------------------------------------------------------------------------
extern "C" void kernel_launch(void* const* d_in, const int* in_sizes, int n_in,
                              void* d_out, int out_size){
    (void)in_sizes; (void)n_in; (void)out_size;
    const float* hs   = (const float*)d_in[0];
    const float* sim  = (const float*)d_in[1];
    const float* gates= (const float*)d_in[2];
    const float* qp   = (const float*)d_in[3];
    const float* kp   = (const float*)d_in[4];
    const float* vp   = (const float*)d_in[5];
    const float* op   = (const float*)d_in[6];
    float* out = (float*)d_out;

    cudaFuncSetAttribute(attn_tc_kernel, cudaFuncAttributeMaxDynamicSharedMemorySize, ATTN_SMEM);
    cudaFuncSetAttribute(fp16_gemm_kernel<NC,512,64,NH,1>, cudaFuncAttributeMaxDynamicSharedMemorySize, GS_TOTAL);
    cudaFuncSetAttribute(fp16_gemm_kernel<NH,64,512,NC,0>, cudaFuncAttributeMaxDynamicSharedMemorySize, GS_TOTAL);

    zero_kernel<<<2048,256>>>(out);
    prep_kernel<<<NE,256>>>(sim,gates);
    conv_w_kernel<<<4096,256>>>(qp,kp,vp,op);
    pack_x_kernel<<<2048,256>>>(hs);
    gate4_kernel<<<dim3(NN/64,4),256>>>(hs);
    gatefin_kernel<<<NN/256,256>>>();
    scan_kernel<<<1,32>>>();
    pairfill_kernel<<<NN/256,256>>>();
    fp16_gemm_kernel<NC,512,64,NH,1><<<dim3(64,3,16),256,GS_TOTAL>>>(nullptr);
    conv_qkv_kernel<<<2048,256>>>();
    attn_tc_kernel<<<dim3(NT/64,NB,2),256,ATTN_SMEM>>>();
    attnfin_kernel<<<NN*32/256,256>>>();
    fp16_gemm_kernel<NH,64,512,NC,0><<<dim3(64,8,16),256,GS_TOTAL>>>(out);
}